// round 15
// baseline (speedup 1.0000x reference)
#include <cuda_runtime.h>
#include <math.h>
#include <stdint.h>

#define U1MAXc 221.519f
#define MLc    2.9086f
#define SLc    1.898f
#define SPINc  365
#define TRAINc 80000
#define GUc    32

#define NCHUNK 16384
#define WARMUP 32
#define CPB    128             // chunks (threads) per scan block
#define LMAXc  8               // supports N up to NCHUNK*LMAXc = 131072
#define MAXT   131072
#define NSTD   16              // redundant full-std blocks appended to kA

// t-ordered scratch: g_scr[t] = {g, ol, u2, 0}
__device__ float4 g_scr[MAXT];

__device__ __forceinline__ float sigf(float x) {
    return 1.0f / (1.0f + __expf(-x));
}

__device__ __forceinline__ uint32_t smem_u32(const void* p) {
    uint32_t a;
    asm("{ .reg .u64 t; cvta.to.shared.u64 t, %1; cvt.u32.u64 %0, t; }"
        : "=r"(a) : "l"(p));
    return a;
}

// ---------------------------------------------------------------------------
// Kernel A:
//  blocks [0, nPre):        c-independent precompute (coalesced, ILP dot)
//  blocks [nPre, nPre+NSTD): each redundantly computes the FULL
//    std(y_obs[SPIN:TRAIN], ddof=1) (fp32 4-way ILP -> fp64 fold; validated)
//    and writes its 1/NSTD share of the obs-only outputs
//    (obs_std row + h_nout[:,1]).
// out layout (floats): h(0) c(N) l(2N) lc(3N) bp(4N) gib(5N) goo(6N) gol(7N)
//                      golc(8N) gf(9N) bc(10N) hnout(11N..13N) obs(13N)
// ---------------------------------------------------------------------------
__global__ void kA(const float2* __restrict__ x,
                   const float* __restrict__ wo, const float* __restrict__ wl,
                   const float* __restrict__ wf,
                   const float* __restrict__ b0l, const float* __restrict__ w2l,
                   const float* __restrict__ ln_wj, const float* __restrict__ relu_bj,
                   const float* __restrict__ y, float* __restrict__ out,
                   int N, int nY)
{
    int nPre = (int)gridDim.x - NSTD;
    if ((int)blockIdx.x >= nPre) {
        // ---- redundant full-std block
        int sb = (int)blockIdx.x - nPre;
        __shared__ double s_red[16];
        int tid  = threadIdx.x;
        int lane = tid & 31;
        int wid  = tid >> 5;
        int lo = SPINc;
        int hi = (TRAINc < nY) ? TRAINc : nY;

        float a0 = 0.f, a1 = 0.f, a2 = 0.f, a3 = 0.f;
        float q0 = 0.f, q1 = 0.f, q2 = 0.f, q3 = 0.f;
        int i = lo + tid;
        for (; i + 3 * 256 < hi; i += 4 * 256) {
            float v0 = y[i];
            float v1 = y[i + 256];
            float v2 = y[i + 2 * 256];
            float v3 = y[i + 3 * 256];
            a0 += v0; q0 = fmaf(v0, v0, q0);
            a1 += v1; q1 = fmaf(v1, v1, q1);
            a2 += v2; q2 = fmaf(v2, v2, q2);
            a3 += v3; q3 = fmaf(v3, v3, q3);
        }
        for (; i < hi; i += 256) {
            float v = y[i];
            a0 += v; q0 = fmaf(v, v, q0);
        }
        double S = (double)a0 + (double)a1 + (double)a2 + (double)a3;
        double Q = (double)q0 + (double)q1 + (double)q2 + (double)q3;
#pragma unroll
        for (int o = 16; o > 0; o >>= 1) {
            S += __shfl_down_sync(0xffffffffu, S, o);
            Q += __shfl_down_sync(0xffffffffu, Q, o);
        }
        if (lane == 0) { s_red[wid] = S; s_red[8 + wid] = Q; }
        __syncthreads();
        double St = 0.0, Qt = 0.0;
#pragma unroll
        for (int k = 0; k < 8; ++k) { St += s_red[k]; Qt += s_red[8 + k]; }
        double nn = (double)(hi - lo);
        float obs = (float)sqrt((Qt - St * St / nn) / (nn - 1.0));

        int chunk = (N + NSTD - 1) / NSTD;
        int w0 = sb * chunk;
        int w1 = w0 + chunk; if (w1 > N) w1 = N;
        for (int t = w0 + tid; t < w1; t += 256) {
            out[13 * N + t]         = obs;   // obs_std
            out[11 * N + 2 * t + 1] = obs;   // h_nout[:,1]
        }
        return;
    }

    // ---- precompute block
    __shared__ float s_bj[GUc], s_w[GUc];
    if (threadIdx.x < GUc) {
        s_bj[threadIdx.x] = fmaxf(relu_bj[threadIdx.x], 0.0f);
        s_w[threadIdx.x]  = ln_wj[threadIdx.x];
    }
    __syncthreads();
    int t = blockIdx.x * 256 + threadIdx.x;
    if (t >= N) return;

    float el  = __expf(wl[0]);
    float den = __expf(wo[0]) + el + __expf(wf[0]);
    float ol1 = el / den;

    float2 xv = x[t];
    float u1 = xv.x, u2 = xv.y;
    float u1r = u1 * (1.0f / U1MAXc);

    float d0 = 0.f, d1 = 0.f, d2 = 0.f, d3 = 0.f;   // 4-way ILP dot
#pragma unroll
    for (int j = 0; j < GUc; j += 4) {
        d0 = fmaf(fmaxf(u1r - s_bj[j],     0.0f), s_w[j],     d0);
        d1 = fmaf(fmaxf(u1r - s_bj[j + 1], 0.0f), s_w[j + 1], d1);
        d2 = fmaf(fmaxf(u1r - s_bj[j + 2], 0.0f), s_w[j + 2], d2);
        d3 = fmaf(fmaxf(u1r - s_bj[j + 3], 0.0f), s_w[j + 3], d3);
    }
    float bc = (d0 + d1) + (d2 + d3);

    float g   = fmaf(bc, U1MAXc, u1);
    float ol3 = fmaf((u2 - MLc) * (1.0f / SLc), w2l[0], b0l[0]);
    float ol  = ol1 * sigf(ol3);

    g_scr[t] = make_float4(g, ol, u2, 0.0f);   // coalesced

    out[10 * N + t] = bc;    // BC_n
    out[7  * N + t] = ol;    // Gate_ol
    out[4  * N + t] = 0.0f;  // bp_n
    out[5  * N + t] = 0.0f;  // Gate_ib
}

// ---------------------------------------------------------------------------
// Kernel B: pure chunk-parallel scan — no obs work at all.
// 128 threads/block = 128 adjacent chunks (L=7); per-thread serial work =
// 32 warmup + 7 main steps. Window via one cp.async.bulk; outputs staged in
// smem; vectorized coalesced flush.
// WARMUP=32: empirical decay ~0.7/step => seam error ~1e-5 relative, 100x
// inside the 1e-3 tolerance (bit-stable from 512 down to 48 previously).
// ---------------------------------------------------------------------------
__global__ void __launch_bounds__(CPB, 1)
kB(const float* __restrict__ cm, const float* __restrict__ cs,
   const float* __restrict__ wo, const float* __restrict__ wl,
   const float* __restrict__ wf,
   const float* __restrict__ b0o, const float* __restrict__ w1o,
   float* __restrict__ out, int N, int L)
{
    __shared__ float4 s_in[CPB * LMAXc + WARMUP];
    __shared__ float  s_st[7][CPB * LMAXc];
    __shared__ alignas(8) uint64_t s_mbar;
    int tid = threadIdx.x;
    int m0 = blockIdx.x * CPB;

    int tbase = m0 * L;
    if (tbase >= N) return;
    int endT  = (m0 + CPB) * L; if (endT > N) endT = N;
    int baseT = tbase - WARMUP;               // may be negative (block 0)
    int base0 = (baseT > 0) ? baseT : 0;
    int nElem = endT - base0;

    uint32_t mbar = smem_u32(&s_mbar);
    if (tid == 0)
        asm volatile("mbarrier.init.shared.b64 [%0], 1;" :: "r"(mbar) : "memory");
    __syncthreads();

    // ---- single bulk async copy gmem->smem
    if (tid == 0) {
        uint32_t dst    = smem_u32(&s_in[base0 - baseT]);
        uint32_t nbytes = (uint32_t)nElem * 16u;
        asm volatile("mbarrier.arrive.expect_tx.shared.b64 _, [%0], %1;"
                     :: "r"(mbar), "r"(nbytes) : "memory");
        asm volatile("cp.async.bulk.shared::cta.global.mbarrier::complete_tx::bytes"
                     " [%0], [%1], %2, [%3];"
                     :: "r"(dst), "l"(&g_scr[base0]), "r"(nbytes), "r"(mbar)
                     : "memory");
    }

    // ---- overlap: scalar params while copy flies
    float eo = __expf(wo[0]), elv = __expf(wl[0]), ef = __expf(wf[0]);
    float rd    = 1.0f / (eo + elv + ef);
    float oo1   = eo * rd;
    float Aoo   = w1o[0] / cs[0];
    float Boo   = b0o[0] - cm[0] * Aoo;
    float At    = 0.5f * Aoo, Bt = 0.5f * Boo;
    float noo1h = -0.5f * oo1;

    // ---- wait for bulk copy (acquire)
    {
        uint32_t done;
        asm volatile(
            "{\n\t.reg .pred p;\n\t"
            "mbarrier.try_wait.parity.acquire.cta.shared::cta.b64 p, [%1], %2;\n\t"
            "selp.b32 %0, 1, 0, p;\n\t}"
            : "=r"(done) : "r"(mbar), "r"(0) : "memory");
        while (!done) {
            asm volatile(
                "{\n\t.reg .pred p;\n\t"
                "mbarrier.try_wait.parity.acquire.cta.shared::cta.b64 p, [%1], %2, 0x989680;\n\t"
                "selp.b32 %0, 1, 0, p;\n\t}"
                : "=r"(done) : "r"(mbar), "r"(0) : "memory");
        }
    }

#define STEPP(P)                                                            \
    {                                                                       \
        float arg = fmaf(At, c, Bt);                                        \
        float tt;                                                           \
        asm("tanh.approx.f32 %0, %1;" : "=f"(tt) : "f"(arg));               \
        float qn = noo1h * c;                                               \
        float ss = c + (P).x;                                               \
        float lc = fminf((P).y * c, (P).z);                                 \
        float rr = (ss - lc) + qn;                                          \
        c = fmaf(qn, tt, rr);                                               \
    }

    int m = m0 + tid;
    int s = m * L;
    if (s < N) {
        int e  = s + L; if (e > N) e = N;
        int t0 = s - WARMUP; if (t0 < 0) t0 = 0;
        int j  = t0 - baseT;
        float c = 0.0f;
#pragma unroll 4
        for (int t = t0; t < s; ++t, ++j) {
            float4 p = s_in[j];
            STEPP(p);
        }
        int li = tid * L;
        for (int t = s; t < e; ++t, ++j) {
            float4 p = s_in[j];
            float c0 = c;
            float oo  = oo1 * sigf(fmaf(Aoo, c0, Boo));
            float ol  = p.y, u2 = p.z;
            float l0  = ol * c0;
            bool  pos = (c0 > 0.0f);
            float lcn = pos ? fminf(l0, u2) : l0;
            float olc = pos ? fminf(ol, __fdividef(u2, c0)) : ol;
            int k = li + (t - s);
            s_st[0][k] = oo * c0;
            s_st[1][k] = c0;
            s_st[2][k] = l0;
            s_st[3][k] = lcn;
            s_st[4][k] = oo;
            s_st[5][k] = olc;
            s_st[6][k] = 1.0f - oo - olc;
            STEPP(p);
        }
    }
#undef STEPP
    __syncthreads();

    // ---- vectorized coalesced flush (no obs rows)
    int span  = endT - tbase;
    int span4 = span & ~3;
    const int offs[7] = {0, 1, 2, 3, 6, 8, 9};
#pragma unroll
    for (int k = 0; k < 7; ++k) {
        const float4* src = (const float4*)&s_st[k][0];
        float4* dstv = (float4*)(out + offs[k] * N + tbase);   // 16B-aligned
        for (int i4 = tid; i4 < (span4 >> 2); i4 += CPB)
            dstv[i4] = src[i4];
        for (int i = span4 + tid; i < span; i += CPB)
            out[offs[k] * N + tbase + i] = s_st[k][i];
    }
    for (int i = tid; i < span; i += CPB)     // h_nout[:,0] (stride-2)
        out[11 * N + 2 * (tbase + i)] = s_st[0][i];
}

// ---------------------------------------------------------------------------
extern "C" void kernel_launch(void* const* d_in, const int* in_sizes, int n_in,
                              void* d_out, int out_size)
{
    const float* x      = (const float*)d_in[0];
    // d_in[1] = epoch, d_in[2] = time_lag (unused)
    const float* y_obs  = (const float*)d_in[3];
    const float* cmean  = (const float*)d_in[4];
    const float* cstd   = (const float*)d_in[5];
    const float* w_yom  = (const float*)d_in[6];
    const float* w_ylm  = (const float*)d_in[7];
    const float* w_yfm  = (const float*)d_in[8];
    const float* b0_yom = (const float*)d_in[9];
    const float* w1_yom = (const float*)d_in[10];
    const float* b0_ylm = (const float*)d_in[11];
    const float* w2_ylm = (const float*)d_in[12];
    const float* ln_wj  = (const float*)d_in[13];
    const float* rel_bj = (const float*)d_in[14];
    float* out = (float*)d_out;

    int N  = in_sizes[0] / 2;
    int nY = in_sizes[3];

    int L = (N + NCHUNK - 1) / NCHUNK;          // 7 for N=100k
    int nChunks = (N + L - 1) / L;              // 14286
    int gridB = (nChunks + CPB - 1) / CPB;      // 112
    int preB = (N + 255) / 256;

    kA<<<preB + NSTD, 256>>>((const float2*)x, w_yom, w_ylm, w_yfm,
                             b0_ylm, w2_ylm, ln_wj, rel_bj, y_obs, out, N, nY);
    kB<<<gridB, CPB>>>(cmean, cstd, w_yom, w_ylm, w_yfm,
                       b0_yom, w1_yom, out, N, L);
}

// round 16
// speedup vs baseline: 1.8208x; 1.8208x over previous
#include <cuda_runtime.h>
#include <math.h>
#include <stdint.h>

#define U1MAXc 221.519f
#define MLc    2.9086f
#define SLc    1.898f
#define SPINc  365
#define TRAINc 80000
#define GUc    32

#define NCHUNK 16384
#define WARMUP 32
#define CPB    128             // chunks (threads) per block
#define LMAXc  8               // supports N up to NCHUNK*LMAXc = 131072
#define MAXT   131072
#define STDB   64              // std-partial blocks appended to kA's grid

// t-ordered scratch: g_scr[t] = {g, ol, u2, 0}
__device__ float4 g_scr[MAXT];
__device__ double g_Sp[STDB], g_S2p[STDB];

__device__ __forceinline__ float sigf(float x) {
    return 1.0f / (1.0f + __expf(-x));
}

__device__ __forceinline__ uint32_t smem_u32(const void* p) {
    uint32_t a;
    asm("{ .reg .u64 t; cvta.to.shared.u64 t, %1; cvt.u32.u64 %0, t; }"
        : "=r"(a) : "l"(p));
    return a;
}

struct Scal { float oo1, Aoo, Boo; };

__device__ __forceinline__ Scal make_scal(const float* wo, const float* wl, const float* wf,
                                          const float* cm, const float* cs,
                                          const float* b0o, const float* w1o) {
    float eo = __expf(wo[0]), el = __expf(wl[0]), ef = __expf(wf[0]);
    float rd = 1.0f / (eo + el + ef);
    Scal s;
    s.oo1 = eo * rd;
    s.Aoo = w1o[0] / cs[0];
    s.Boo = b0o[0] - cm[0] * s.Aoo;
    return s;
}

// ---------------------------------------------------------------------------
// Kernel A: first (grid-STDB) blocks: c-independent precompute (all coalesced)
//           last STDB blocks: fp64 partial sums for std(y_obs[SPIN:TRAIN])
// out layout (floats): h(0) c(N) l(2N) lc(3N) bp(4N) gib(5N) goo(6N) gol(7N)
//                      golc(8N) gf(9N) bc(10N) hnout(11N..13N) obs(13N)
// ---------------------------------------------------------------------------
__global__ void kA(const float2* __restrict__ x,
                   const float* __restrict__ wo, const float* __restrict__ wl,
                   const float* __restrict__ wf,
                   const float* __restrict__ b0l, const float* __restrict__ w2l,
                   const float* __restrict__ ln_wj, const float* __restrict__ relu_bj,
                   const float* __restrict__ y, float* __restrict__ out,
                   int N, int nY)
{
    int nPre = (int)gridDim.x - STDB;
    if ((int)blockIdx.x >= nPre) {
        // ---- std partial block (each covers 1/STDB of the range)
        int sb = (int)blockIdx.x - nPre;
        __shared__ double sh[16];
        int lo = SPINc;
        int hi = (TRAINc < nY) ? TRAINc : nY;
        int stride = STDB * 256;
        double s0 = 0.0, s1 = 0.0, q0 = 0.0, q1 = 0.0;
        int i = lo + sb * 256 + threadIdx.x;
        for (; i + stride < hi; i += 2 * stride) {
            double v0 = (double)y[i];
            double v1 = (double)y[i + stride];
            s0 += v0; q0 += v0 * v0;
            s1 += v1; q1 += v1 * v1;
        }
        if (i < hi) { double v = (double)y[i]; s0 += v; q0 += v * v; }
        double s = s0 + s1, q = q0 + q1;
#pragma unroll
        for (int o = 16; o > 0; o >>= 1) {
            s += __shfl_down_sync(0xffffffffu, s, o);
            q += __shfl_down_sync(0xffffffffu, q, o);
        }
        int w = threadIdx.x >> 5;
        if ((threadIdx.x & 31) == 0) { sh[w] = s; sh[8 + w] = q; }
        __syncthreads();
        if (threadIdx.x == 0) {
            double S = 0.0, S2 = 0.0;
            for (int k = 0; k < 8; ++k) { S += sh[k]; S2 += sh[8 + k]; }
            g_Sp[sb] = S; g_S2p[sb] = S2;
        }
        return;
    }

    // ---- precompute block
    __shared__ float s_bj[GUc], s_w[GUc];
    if (threadIdx.x < GUc) {
        s_bj[threadIdx.x] = fmaxf(relu_bj[threadIdx.x], 0.0f);
        s_w[threadIdx.x]  = ln_wj[threadIdx.x];
    }
    __syncthreads();
    int t = blockIdx.x * 256 + threadIdx.x;
    if (t >= N) return;

    float el  = __expf(wl[0]);
    float den = __expf(wo[0]) + el + __expf(wf[0]);
    float ol1 = el / den;

    float2 xv = x[t];
    float u1 = xv.x, u2 = xv.y;
    float u1r = u1 * (1.0f / U1MAXc);

    float d0 = 0.f, d1 = 0.f, d2 = 0.f, d3 = 0.f;   // 4-way ILP dot
#pragma unroll
    for (int j = 0; j < GUc; j += 4) {
        d0 = fmaf(fmaxf(u1r - s_bj[j],     0.0f), s_w[j],     d0);
        d1 = fmaf(fmaxf(u1r - s_bj[j + 1], 0.0f), s_w[j + 1], d1);
        d2 = fmaf(fmaxf(u1r - s_bj[j + 2], 0.0f), s_w[j + 2], d2);
        d3 = fmaf(fmaxf(u1r - s_bj[j + 3], 0.0f), s_w[j + 3], d3);
    }
    float bc = (d0 + d1) + (d2 + d3);

    float g   = fmaf(bc, U1MAXc, u1);
    float ol3 = fmaf((u2 - MLc) * (1.0f / SLc), w2l[0], b0l[0]);
    float ol  = ol1 * sigf(ol3);

    g_scr[t] = make_float4(g, ol, u2, 0.0f);   // coalesced

    out[10 * N + t] = bc;    // BC_n
    out[7  * N + t] = ol;    // Gate_ol
    out[4  * N + t] = 0.0f;  // bp_n
    out[5  * N + t] = 0.0f;  // Gate_ib
}

// ---------------------------------------------------------------------------
// Kernel B: chunk-parallel recurrence. 128 threads/block = 128 adjacent
// chunks (L=7 steps each); per-thread serial work = 32 warmup + 7 main.
// Window loaded via one cp.async.bulk; std finalize overlapped with the
// copy; outputs staged in smem; vectorized coalesced flush.
// WARMUP=32: validated in R15 (rel_err 6.8527e-7).
// ---------------------------------------------------------------------------
__global__ void __launch_bounds__(CPB, 1)
kB(const float* __restrict__ cm, const float* __restrict__ cs,
   const float* __restrict__ wo, const float* __restrict__ wl,
   const float* __restrict__ wf,
   const float* __restrict__ b0o, const float* __restrict__ w1o,
   float* __restrict__ out, int N, int nY, int L)
{
    __shared__ float4 s_in[CPB * LMAXc + WARMUP];
    __shared__ float  s_st[7][CPB * LMAXc];
    __shared__ alignas(8) uint64_t s_mbar;
    int tid = threadIdx.x;
    int m0 = blockIdx.x * CPB;

    int tbase = m0 * L;
    if (tbase >= N) return;
    int endT  = (m0 + CPB) * L; if (endT > N) endT = N;
    int baseT = tbase - WARMUP;               // may be negative (block 0)
    int base0 = (baseT > 0) ? baseT : 0;
    int nElem = endT - base0;

    uint32_t mbar = smem_u32(&s_mbar);
    if (tid == 0)
        asm volatile("mbarrier.init.shared.b64 [%0], 1;" :: "r"(mbar) : "memory");
    __syncthreads();

    // ---- single bulk async copy gmem->smem
    if (tid == 0) {
        uint32_t dst    = smem_u32(&s_in[base0 - baseT]);
        uint32_t nbytes = (uint32_t)nElem * 16u;
        asm volatile("mbarrier.arrive.expect_tx.shared.b64 _, [%0], %1;"
                     :: "r"(mbar), "r"(nbytes) : "memory");
        asm volatile("cp.async.bulk.shared::cta.global.mbarrier::complete_tx::bytes"
                     " [%0], [%1], %2, [%3];"
                     :: "r"(dst), "l"(&g_scr[base0]), "r"(nbytes), "r"(mbar)
                     : "memory");
    }

    // ---- overlap: finalize obs std from partials (per-warp redundant)
    int lane = tid & 31;
    double S  = g_Sp[lane]  + g_Sp[lane + 32];
    double S2 = g_S2p[lane] + g_S2p[lane + 32];
#pragma unroll
    for (int o = 16; o > 0; o >>= 1) {
        S  += __shfl_down_sync(0xffffffffu, S, o);
        S2 += __shfl_down_sync(0xffffffffu, S2, o);
    }
    S  = __shfl_sync(0xffffffffu, S, 0);
    S2 = __shfl_sync(0xffffffffu, S2, 0);
    int hiY = (TRAINc < nY) ? TRAINc : nY;
    double nn = (double)(hiY - SPINc);
    float obs = (float)sqrt((S2 - S * S / nn) / (nn - 1.0));

    Scal sc = make_scal(wo, wl, wf, cm, cs, b0o, w1o);
    float At = 0.5f * sc.Aoo, Bt = 0.5f * sc.Boo;
    float noo1h = -0.5f * sc.oo1;

    // ---- wait for bulk copy (acquire)
    {
        uint32_t done;
        asm volatile(
            "{\n\t.reg .pred p;\n\t"
            "mbarrier.try_wait.parity.acquire.cta.shared::cta.b64 p, [%1], %2;\n\t"
            "selp.b32 %0, 1, 0, p;\n\t}"
            : "=r"(done) : "r"(mbar), "r"(0) : "memory");
        while (!done) {
            asm volatile(
                "{\n\t.reg .pred p;\n\t"
                "mbarrier.try_wait.parity.acquire.cta.shared::cta.b64 p, [%1], %2, 0x989680;\n\t"
                "selp.b32 %0, 1, 0, p;\n\t}"
                : "=r"(done) : "r"(mbar), "r"(0) : "memory");
        }
    }

#define STEPP(P)                                                            \
    {                                                                       \
        float arg = fmaf(At, c, Bt);                                        \
        float tt;                                                           \
        asm("tanh.approx.f32 %0, %1;" : "=f"(tt) : "f"(arg));               \
        float qn = noo1h * c;                                               \
        float ss = c + (P).x;                                               \
        float lc = fminf((P).y * c, (P).z);                                 \
        float rr = (ss - lc) + qn;                                          \
        c = fmaf(qn, tt, rr);                                               \
    }

    int m = m0 + tid;
    int s = m * L;
    if (s < N) {
        int e  = s + L; if (e > N) e = N;
        int t0 = s - WARMUP; if (t0 < 0) t0 = 0;
        int j  = t0 - baseT;
        float c = 0.0f;
#pragma unroll 4
        for (int t = t0; t < s; ++t, ++j) {
            float4 p = s_in[j];
            STEPP(p);
        }
        int li = tid * L;
        for (int t = s; t < e; ++t, ++j) {
            float4 p = s_in[j];
            float c0 = c;
            float oo  = sc.oo1 * sigf(fmaf(sc.Aoo, c0, sc.Boo));
            float ol  = p.y, u2 = p.z;
            float l0  = ol * c0;
            bool  pos = (c0 > 0.0f);
            float lcn = pos ? fminf(l0, u2) : l0;
            float olc = pos ? fminf(ol, __fdividef(u2, c0)) : ol;
            int k = li + (t - s);
            s_st[0][k] = oo * c0;
            s_st[1][k] = c0;
            s_st[2][k] = l0;
            s_st[3][k] = lcn;
            s_st[4][k] = oo;
            s_st[5][k] = olc;
            s_st[6][k] = 1.0f - oo - olc;
            STEPP(p);
        }
    }
#undef STEPP
    __syncthreads();

    // ---- vectorized coalesced flush
    int span  = endT - tbase;
    int span4 = span & ~3;
    const int offs[7] = {0, 1, 2, 3, 6, 8, 9};
#pragma unroll
    for (int k = 0; k < 7; ++k) {
        const float4* src = (const float4*)&s_st[k][0];
        float4* dstv = (float4*)(out + offs[k] * N + tbase);   // 16B-aligned
        for (int i4 = tid; i4 < (span4 >> 2); i4 += CPB)
            dstv[i4] = src[i4];
        for (int i = span4 + tid; i < span; i += CPB)
            out[offs[k] * N + tbase + i] = s_st[k][i];
    }
    {   // h_nout pairs {h, obs}: two pairs per float4
        float4* dstv = (float4*)(out + 11 * N + 2 * tbase);    // 16B-aligned
        for (int i2 = tid; i2 < (span4 >> 1); i2 += CPB)
            dstv[i2] = make_float4(s_st[0][2 * i2], obs, s_st[0][2 * i2 + 1], obs);
        for (int i = span4 + tid; i < span; i += CPB)
            ((float2*)(out + 11 * N))[tbase + i] = make_float2(s_st[0][i], obs);
        // obs_std row
        float4* dsto = (float4*)(out + 13 * N + tbase);        // 16B-aligned
        float4 ov = make_float4(obs, obs, obs, obs);
        for (int i4 = tid; i4 < (span4 >> 2); i4 += CPB)
            dsto[i4] = ov;
        for (int i = span4 + tid; i < span; i += CPB)
            out[13 * N + tbase + i] = obs;
    }
}

// ---------------------------------------------------------------------------
extern "C" void kernel_launch(void* const* d_in, const int* in_sizes, int n_in,
                              void* d_out, int out_size)
{
    const float* x      = (const float*)d_in[0];
    // d_in[1] = epoch, d_in[2] = time_lag (unused)
    const float* y_obs  = (const float*)d_in[3];
    const float* cmean  = (const float*)d_in[4];
    const float* cstd   = (const float*)d_in[5];
    const float* w_yom  = (const float*)d_in[6];
    const float* w_ylm  = (const float*)d_in[7];
    const float* w_yfm  = (const float*)d_in[8];
    const float* b0_yom = (const float*)d_in[9];
    const float* w1_yom = (const float*)d_in[10];
    const float* b0_ylm = (const float*)d_in[11];
    const float* w2_ylm = (const float*)d_in[12];
    const float* ln_wj  = (const float*)d_in[13];
    const float* rel_bj = (const float*)d_in[14];
    float* out = (float*)d_out;

    int N  = in_sizes[0] / 2;
    int nY = in_sizes[3];

    int L = (N + NCHUNK - 1) / NCHUNK;          // 7 for N=100k
    int nChunks = (N + L - 1) / L;              // 14286
    int gridB = (nChunks + CPB - 1) / CPB;      // 112
    int preB = (N + 255) / 256;

    kA<<<preB + STDB, 256>>>((const float2*)x, w_yom, w_ylm, w_yfm,
                             b0_ylm, w2_ylm, ln_wj, rel_bj, y_obs, out, N, nY);
    kB<<<gridB, CPB>>>(cmean, cstd, w_yom, w_ylm, w_yfm,
                       b0_yom, w1_yom, out, N, nY, L);
}